// round 9
// baseline (speedup 1.0000x reference)
#include <cuda_runtime.h>
#include <cuda_bf16.h>
#include <cstdint>

#define GRAPHS 4096
#define NPG 18
#define NNODES (GRAPHS * NPG)
#define FIN 1536
#define EPERG 306
#define SLOPE 0.01f
#define BN_EPS 1e-5f

#define NKSTEP (FIN / 16)            // 96 k-steps of 16
#define GPC 4                        // graphs per CTA (graph_kernel)

// Scratch
__device__ float g_P1[(size_t)NNODES * 32];
__device__ uint32_t g_fragH[NKSTEP * 256];
__device__ uint32_t g_fragL[NKSTEP * 256];

// ---------------------------------------------------------------------------
__device__ __forceinline__ void mma16816(float* c, const uint32_t* a, const uint32_t* b) {
    asm volatile("mma.sync.aligned.m16n8k16.row.col.f32.bf16.bf16.f32 "
        "{%0,%1,%2,%3}, {%4,%5,%6,%7}, {%8,%9}, {%0,%1,%2,%3};"
        : "+f"(c[0]), "+f"(c[1]), "+f"(c[2]), "+f"(c[3])
        : "r"(a[0]), "r"(a[1]), "r"(a[2]), "r"(a[3]), "r"(b[0]), "r"(b[1]));
}
__device__ __forceinline__ uint32_t pack_bf16x2(float lo, float hi) {
    uint32_t r;
    asm("cvt.rn.bf16x2.f32 %0, %1, %2;" : "=r"(r) : "f"(hi), "f"(lo));
    return r;
}
__device__ __forceinline__ void split2(float2 v, uint32_t& hi, uint32_t& lo) {
    hi = pack_bf16x2(v.x, v.y);
    float f0 = __uint_as_float(hi << 16);
    float f1 = __uint_as_float(hi & 0xFFFF0000u);
    lo = pack_bf16x2(v.x - f0, v.y - f1);
}
__device__ __forceinline__ float lrelu(float v) { return v >= 0.f ? v : SLOPE * v; }

// ---- packed f32x2 helpers ----
__device__ __forceinline__ uint64_t bcast2(float a) {
    uint64_t r;
    asm("mov.b64 %0, {%1, %1};" : "=l"(r) : "f"(a));
    return r;
}
__device__ __forceinline__ uint64_t ffma2(uint64_t a, uint64_t b, uint64_t c) {
    uint64_t d;
    asm("fma.rn.f32x2 %0, %1, %2, %3;" : "=l"(d) : "l"(a), "l"(b), "l"(c));
    return d;
}
__device__ __forceinline__ float2 unpack2(uint64_t v) {
    float2 f;
    asm("mov.b64 {%0, %1}, %2;" : "=f"(f.x), "=f"(f.y) : "l"(v));
    return f;
}
__device__ __forceinline__ float4 up4(ulonglong2 v) {
    float2 a = unpack2(v.x), b = unpack2(v.y);
    return make_float4(a.x, a.y, b.x, b.y);
}
__device__ __forceinline__ float4 bn_lrelu4(float4 acc, float4 bb, float4 s, float4 t) {
    float4 o;
    o.x = lrelu(fmaf(acc.x + bb.x, s.x, t.x));
    o.y = lrelu(fmaf(acc.y + bb.y, s.y, t.y));
    o.z = lrelu(fmaf(acc.z + bb.z, s.z, t.z));
    o.w = lrelu(fmaf(acc.w + bb.w, s.w, t.w));
    return o;
}

// ---------------------------------------------------------------------------
// Kernel 0: W1 fragment builder (identical to R5/R8).
// ---------------------------------------------------------------------------
__global__ __launch_bounds__(256) void wconv_kernel(const float* __restrict__ W1) {
    int t = blockIdx.x * 256 + threadIdx.x;
    int s = t >> 6;
    int rem = t & 63;
    int j = rem >> 5, lane = rem & 31;
    uint32_t h[4], l[4];
#pragma unroll
    for (int i = 0; i < 4; i++) {
        int ri = j * 4 + i;
        int nt = ri >> 1, which = ri & 1;
        int n = nt * 8 + (lane >> 2);
        int k = s * 16 + (lane & 3) * 2 + which * 8;
        float x0 = W1[(size_t)k * 32 + n];
        float x1 = W1[(size_t)(k + 1) * 32 + n];
        split2(make_float2(x0, x1), h[i], l[i]);
    }
    int o = s * 256 + j * 128 + lane * 4;
    *(uint4*)(g_fragH + o) = make_uint4(h[0], h[1], h[2], h[3]);
    *(uint4*)(g_fragL + o) = make_uint4(l[0], l[1], l[2], l[3]);
}

// ---------------------------------------------------------------------------
// Kernel 1: P1 = X @ W1 (identical to R5/R8).
// ---------------------------------------------------------------------------
__global__ __launch_bounds__(256) void gemm1_mma_kernel(const float* __restrict__ X)
{
    const int tid = threadIdx.x;
    const int wid = tid >> 5;
    const int lane = tid & 31;
    const int row0 = blockIdx.x * 128;
    const int r = row0 + wid * 16 + (lane >> 2);

    const float* xr0 = X + (size_t)r * FIN + (lane & 3) * 2;
    const float* xr1 = xr0 + (size_t)8 * FIN;
    const uint4* fH = (const uint4*)g_fragH + lane;
    const uint4* fL = (const uint4*)g_fragL + lane;

    float acc[4][4];
#pragma unroll
    for (int nt = 0; nt < 4; nt++)
#pragma unroll
        for (int q = 0; q < 4; q++) acc[nt][q] = 0.f;

#pragma unroll 2
    for (int s = 0; s < NKSTEP; s++) {
        const int k = s * 16;
        float2 a0 = *(const float2*)(xr0 + k);
        float2 a1 = *(const float2*)(xr1 + k);
        float2 a2 = *(const float2*)(xr0 + k + 8);
        float2 a3 = *(const float2*)(xr1 + k + 8);
        uint4 h0 = fH[s * 64];
        uint4 h1 = fH[s * 64 + 32];
        uint4 l0 = fL[s * 64];
        uint4 l1 = fL[s * 64 + 32];

        uint32_t ahi[4], alo[4];
        split2(a0, ahi[0], alo[0]);
        split2(a1, ahi[1], alo[1]);
        split2(a2, ahi[2], alo[2]);
        split2(a3, ahi[3], alo[3]);

        uint32_t bhi[8] = {h0.x, h0.y, h0.z, h0.w, h1.x, h1.y, h1.z, h1.w};
        uint32_t blo[8] = {l0.x, l0.y, l0.z, l0.w, l1.x, l1.y, l1.z, l1.w};

#pragma unroll
        for (int nt = 0; nt < 4; nt++) {
            mma16816(acc[nt], ahi, bhi + nt * 2);
            mma16816(acc[nt], ahi, blo + nt * 2);
            mma16816(acc[nt], alo, bhi + nt * 2);
        }
    }

    {
        int cb = (lane & 3) * 2;
#pragma unroll
        for (int nt = 0; nt < 4; nt++) {
            *(float2*)(g_P1 + (size_t)r * 32 + nt * 8 + cb) =
                make_float2(acc[nt][0], acc[nt][1]);
            *(float2*)(g_P1 + (size_t)(r + 8) * 32 + nt * 8 + cb) =
                make_float2(acc[nt][2], acc[nt][3]);
        }
    }
}

// ---------------------------------------------------------------------------
// Kernel 2: FOUR graphs per CTA (1024 CTAs, 288 threads).
// W loads amortized 4x; packed FFMA2 math; buffer overlays.
// ---------------------------------------------------------------------------
__global__ __launch_bounds__(288, 3) void graph_kernel(
    const float* __restrict__ ew,
    const float* __restrict__ b1, const float* __restrict__ g1,
    const float* __restrict__ be1, const float* __restrict__ rm1, const float* __restrict__ rv1,
    const float* __restrict__ W2, const float* __restrict__ b2, const float* __restrict__ g2,
    const float* __restrict__ be2, const float* __restrict__ rm2, const float* __restrict__ rv2,
    const float* __restrict__ W3, const float* __restrict__ b3, const float* __restrict__ g3,
    const float* __restrict__ be3, const float* __restrict__ rm3, const float* __restrict__ rv3,
    const float* __restrict__ fW1, const float* __restrict__ fb1,
    const float* __restrict__ fW2, const float* __restrict__ fb2,
    const float* __restrict__ fW3, const float* __restrict__ fb3,
    const float* __restrict__ fW4, const float* __restrict__ fb4,
    float* __restrict__ out)
{
    __shared__ __align__(16) float As[GPC * 360];        // A[g][c][r]: g*360+c*20+r
    __shared__ __align__(16) float bufA[GPC * 18 * 64];  // 4608 ; p2 overlay
    __shared__ __align__(16) float bufB[GPC * 18 * 64];  // 4608 ; Wm + part overlay
    __shared__ float dinv[GPC * 18];
    __shared__ __align__(16) float bns1[32], bnb1[32];
    __shared__ __align__(16) float bns2[64], bnb2[64];
    __shared__ __align__(16) float bns3[128], bnb3[128];
    __shared__ __align__(16) float pvec[GPC * 128];
    __shared__ float m1[GPC * 64], m2[GPC * 32], m3[GPC * 16];

    float* Wm  = bufB;    // overlay during adjacency build
    float* part = bufB;   // overlay during layer3 GEMM: cg*512 + g*128 + f
    float* p2  = bufA;    // overlay during MLP: ks*256 + g*64 + f

    const int g0 = blockIdx.x * GPC;
    const int tid = threadIdx.x;

    // --- BN fold ---
    if (tid < 32) {
        float s = g1[tid] * rsqrtf(rv1[tid] + BN_EPS);
        bns1[tid] = s; bnb1[tid] = be1[tid] - rm1[tid] * s;
    } else if (tid < 96) {
        int f = tid - 32;
        float s = g2[f] * rsqrtf(rv2[f] + BN_EPS);
        bns2[f] = s; bnb2[f] = be2[f] - rm2[f] * s;
    } else if (tid < 224) {
        int f = tid - 96;
        float s = g3[f] * rsqrtf(rv3[f] + BN_EPS);
        bns3[f] = s; bnb3[f] = be3[f] - rm3[f] * s;
    }

    // --- adjacency (Wm overlays bufB) ---
    for (int t = tid; t < GPC * 324; t += 288) {
        int g = t / 324, rem = t - g * 324;
        int s = rem / 18, d = rem - s * 18;
        Wm[g * 360 + s * 20 + d] = (s == d) ? 1.0f
            : ew[(size_t)(g0 + g) * EPERG + s * 17 + d - (d > s ? 1 : 0)];
    }
    // load P1 -> bufA[g][r][0..31]
#pragma unroll
    for (int p = 0; p < 2; p++) {
        int idx = tid + p * 288;             // 576 tasks
        int g = idx / 144, rem = idx - g * 144;
        int r = rem >> 3, f4 = rem & 7;
        *(float4*)&bufA[(g * 18 + r) * 64 + f4 * 4] =
            *(const float4*)(g_P1 + ((size_t)(g0 + g) * 18 + r) * 32 + f4 * 4);
    }
    __syncthreads();
    if (tid < GPC * 18) {
        int g = tid / 18, c = tid - g * 18;
        float sum = 0.f;
#pragma unroll
        for (int s = 0; s < 18; s++) sum += Wm[g * 360 + s * 20 + c];
        dinv[tid] = rsqrtf(sum);
    }
    __syncthreads();
    for (int t = tid; t < GPC * 324; t += 288) {
        int g = t / 324, rem = t - g * 324;
        int c = rem / 18, r = rem - c * 18;
        As[g * 360 + c * 20 + r] = dinv[g * 18 + r] * dinv[g * 18 + c]
                                 * Wm[g * 360 + r * 20 + c];
    }
    __syncthreads();

    // --- layer1: h1 = lrelu(bn1(A @ P1 + b1)) -> bufB (width 32) ---
#pragma unroll
    for (int p = 0; p < 2; p++) {
        int idx = tid + p * 288;
        int g = idx / 144, rem = idx - g * 144;
        int c = rem >> 3, f4 = rem & 7;
        ulonglong2 acc = make_ulonglong2(0ULL, 0ULL);
#pragma unroll
        for (int r = 0; r < 18; r++) {
            uint64_t av = bcast2(As[g * 360 + c * 20 + r]);
            ulonglong2 h = *(const ulonglong2*)&bufA[(g * 18 + r) * 64 + f4 * 4];
            acc.x = ffma2(av, h.x, acc.x);
            acc.y = ffma2(av, h.y, acc.y);
        }
        float4 o = bn_lrelu4(up4(acc), __ldg((const float4*)b1 + f4),
                             *(float4*)&bns1[f4 * 4], *(float4*)&bnb1[f4 * 4]);
        *(float4*)&bufB[(g * 18 + c) * 64 + f4 * 4] = o;
    }
    __syncthreads();

    // --- layer2 agg-first: g2m = A @ h1 -> bufA (width 32) ---
#pragma unroll
    for (int p = 0; p < 2; p++) {
        int idx = tid + p * 288;
        int g = idx / 144, rem = idx - g * 144;
        int c = rem >> 3, f4 = rem & 7;
        ulonglong2 acc = make_ulonglong2(0ULL, 0ULL);
#pragma unroll
        for (int r = 0; r < 18; r++) {
            uint64_t av = bcast2(As[g * 360 + c * 20 + r]);
            ulonglong2 h = *(const ulonglong2*)&bufB[(g * 18 + r) * 64 + f4 * 4];
            acc.x = ffma2(av, h.x, acc.x);
            acc.y = ffma2(av, h.y, acc.y);
        }
        *(ulonglong2*)&bufA[(g * 18 + c) * 64 + f4 * 4] = acc;
    }
    __syncthreads();

    // --- layer2 GEMM: h2 = lrelu(bn2(g2m @ W2 + b2)) -> bufB (width 64),
    //     one W2 load feeds 4 graphs ---
    {
        int c = tid >> 4, f4 = tid & 15;     // 18 x 16 = 288
        ulonglong2 acc[GPC];
#pragma unroll
        for (int g = 0; g < GPC; g++) acc[g] = make_ulonglong2(0ULL, 0ULL);
#pragma unroll 4
        for (int k = 0; k < 32; k++) {
            ulonglong2 w = __ldg((const ulonglong2*)(W2 + (size_t)k * 64) + f4);
#pragma unroll
            for (int g = 0; g < GPC; g++) {
                uint64_t a = bcast2(bufA[(g * 18 + c) * 64 + k]);
                acc[g].x = ffma2(a, w.x, acc[g].x);
                acc[g].y = ffma2(a, w.y, acc[g].y);
            }
        }
        float4 bb = __ldg((const float4*)b2 + f4);
        float4 s = *(float4*)&bns2[f4 * 4];
        float4 t = *(float4*)&bnb2[f4 * 4];
#pragma unroll
        for (int g = 0; g < GPC; g++)
            *(float4*)&bufB[(g * 18 + c) * 64 + f4 * 4] = bn_lrelu4(up4(acc[g]), bb, s, t);
    }
    __syncthreads();

    // --- layer3 agg-first: g3m = A @ h2 -> bufA (width 64) ---
    {
        int c = tid >> 4, f4 = tid & 15;
#pragma unroll
        for (int g = 0; g < GPC; g++) {
            ulonglong2 acc = make_ulonglong2(0ULL, 0ULL);
#pragma unroll
            for (int r = 0; r < 18; r++) {
                uint64_t av = bcast2(As[g * 360 + c * 20 + r]);
                ulonglong2 h = *(const ulonglong2*)&bufB[(g * 18 + r) * 64 + f4 * 4];
                acc.x = ffma2(av, h.x, acc.x);
                acc.y = ffma2(av, h.y, acc.y);
            }
            *(ulonglong2*)&bufA[(g * 18 + c) * 64 + f4 * 4] = acc;
        }
    }
    __syncthreads();

    // --- layer3 GEMM + BN + lrelu + pool partial; one W3 load feeds 8 outputs ---
    // part overlays bufB: cg*512 + g*128 + f
    {
        int cg = tid >> 5, f4 = tid & 31;    // 9 warps x 32 lanes
        int ra = cg * 2, rb = ra + 1;
        ulonglong2 pa[GPC], pb[GPC];
#pragma unroll
        for (int g = 0; g < GPC; g++) {
            pa[g] = make_ulonglong2(0ULL, 0ULL);
            pb[g] = make_ulonglong2(0ULL, 0ULL);
        }
#pragma unroll 4
        for (int k = 0; k < 64; k++) {
            ulonglong2 w = __ldg((const ulonglong2*)(W3 + (size_t)k * 128) + f4);
#pragma unroll
            for (int g = 0; g < GPC; g++) {
                uint64_t va = bcast2(bufA[(g * 18 + ra) * 64 + k]);
                uint64_t vb = bcast2(bufA[(g * 18 + rb) * 64 + k]);
                pa[g].x = ffma2(va, w.x, pa[g].x); pa[g].y = ffma2(va, w.y, pa[g].y);
                pb[g].x = ffma2(vb, w.x, pb[g].x); pb[g].y = ffma2(vb, w.y, pb[g].y);
            }
        }
        float4 bb = __ldg((const float4*)b3 + f4);
        float4 s = *(float4*)&bns3[f4 * 4];
        float4 t = *(float4*)&bnb3[f4 * 4];
        __syncthreads();   // bufB (h2) reads done everywhere before part overlay
#pragma unroll
        for (int g = 0; g < GPC; g++) {
            float4 oa = bn_lrelu4(up4(pa[g]), bb, s, t);
            float4 ob = bn_lrelu4(up4(pb[g]), bb, s, t);
            *(float4*)&part[cg * 512 + g * 128 + f4 * 4] =
                make_float4(oa.x + ob.x, oa.y + ob.y, oa.z + ob.z, oa.w + ob.w);
        }
    }
    __syncthreads();

    // --- pool reduce: pvec[g][f] = (sum over 9 warps) / 18 ---
#pragma unroll
    for (int p = 0; p < 2; p++) {
        int idx = tid + p * 288;             // 512 tasks
        if (idx < GPC * 128) {
            int g = idx >> 7, f = idx & 127;
            float s = 0.f;
#pragma unroll
            for (int cg = 0; cg < 9; cg++) s += part[cg * 512 + g * 128 + f];
            pvec[g * 128 + f] = s * (1.0f / 18.0f);
        }
    }
    __syncthreads();

    // --- MLP head. fW1: 4-way k-split x 64 f, each thread does all 4 graphs ---
    if (tid < 256) {
        int ks = tid >> 6, f = tid & 63;
        float a0 = 0.f, a1 = 0.f, a2 = 0.f, a3 = 0.f;
#pragma unroll 8
        for (int k = ks * 32; k < ks * 32 + 32; k++) {
            float w = __ldg(fW1 + (size_t)k * 64 + f);
            a0 = fmaf(pvec[0 * 128 + k], w, a0);
            a1 = fmaf(pvec[1 * 128 + k], w, a1);
            a2 = fmaf(pvec[2 * 128 + k], w, a2);
            a3 = fmaf(pvec[3 * 128 + k], w, a3);
        }
        p2[ks * 256 + 0 * 64 + f] = a0;
        p2[ks * 256 + 1 * 64 + f] = a1;
        p2[ks * 256 + 2 * 64 + f] = a2;
        p2[ks * 256 + 3 * 64 + f] = a3;
    }
    __syncthreads();
    if (tid < 256) {
        int g = tid >> 6, f = tid & 63;
        m1[g * 64 + f] = lrelu(p2[0 * 256 + g * 64 + f] + p2[1 * 256 + g * 64 + f]
                             + p2[2 * 256 + g * 64 + f] + p2[3 * 256 + g * 64 + f]
                             + __ldg(fb1 + f));
    }
    __syncthreads();
    if (tid < GPC * 32) {
        int g = tid >> 5, f = tid & 31;
        float acc = __ldg(fb2 + f);
#pragma unroll 8
        for (int k = 0; k < 64; k++)
            acc = fmaf(m1[g * 64 + k], __ldg(fW2 + (size_t)k * 32 + f), acc);
        m2[g * 32 + f] = lrelu(acc);
    }
    __syncthreads();
    if (tid < GPC * 16) {
        int g = tid >> 4, f = tid & 15;
        float acc = __ldg(fb3 + f);
#pragma unroll
        for (int k = 0; k < 32; k++)
            acc = fmaf(m2[g * 32 + k], __ldg(fW3 + (size_t)k * 16 + f), acc);
        m3[g * 16 + f] = lrelu(acc);
    }
    __syncthreads();
    {
        int wid = tid >> 5, lane = tid & 31;
        if (wid < GPC) {
            float p = (lane < 16) ? m3[wid * 16 + lane] * __ldg(fW4 + lane) : 0.f;
#pragma unroll
            for (int off = 8; off > 0; off >>= 1)
                p += __shfl_down_sync(0xFFFFFFFFu, p, off);
            if (lane == 0) out[g0 + wid] = p + __ldg(fb4);
        }
    }
}

// ---------------------------------------------------------------------------
extern "C" void kernel_launch(void* const* d_in, const int* in_sizes, int n_in,
                              void* d_out, int out_size)
{
    (void)in_sizes; (void)n_in; (void)out_size;
    const float* x   = (const float*)d_in[0];
    const float* ew  = (const float*)d_in[2];
    const float* W1  = (const float*)d_in[4];
    const float* b1  = (const float*)d_in[5];
    const float* g1  = (const float*)d_in[6];
    const float* be1 = (const float*)d_in[7];
    const float* rm1 = (const float*)d_in[8];
    const float* rv1 = (const float*)d_in[9];
    const float* W2  = (const float*)d_in[10];
    const float* b2  = (const float*)d_in[11];
    const float* g2  = (const float*)d_in[12];
    const float* be2 = (const float*)d_in[13];
    const float* rm2 = (const float*)d_in[14];
    const float* rv2 = (const float*)d_in[15];
    const float* W3  = (const float*)d_in[16];
    const float* b3  = (const float*)d_in[17];
    const float* g3  = (const float*)d_in[18];
    const float* be3 = (const float*)d_in[19];
    const float* rm3 = (const float*)d_in[20];
    const float* rv3 = (const float*)d_in[21];
    const float* fW1 = (const float*)d_in[22];
    const float* fb1 = (const float*)d_in[23];
    const float* fW2 = (const float*)d_in[24];
    const float* fb2 = (const float*)d_in[25];
    const float* fW3 = (const float*)d_in[26];
    const float* fb3 = (const float*)d_in[27];
    const float* fW4 = (const float*)d_in[28];
    const float* fb4 = (const float*)d_in[29];

    wconv_kernel<<<24, 256>>>(W1);
    gemm1_mma_kernel<<<NNODES / 128, 256>>>(x);
    graph_kernel<<<GRAPHS / GPC, 288>>>(ew,
        b1, g1, be1, rm1, rv1,
        W2, b2, g2, be2, rm2, rv2,
        W3, b3, g3, be3, rm3, rv3,
        fW1, fb1, fW2, fb2, fW3, fb3, fW4, fb4,
        (float*)d_out);
}